// round 14
// baseline (speedup 1.0000x reference)
#include <cuda_runtime.h>
#include <cuda_fp16.h>
#include <mma.h>
#include <cstdint>

using namespace nvcuda;

// Problem constants
#define Bn  4
#define SQn 2048
#define SKn 2048
#define Dn  1024
#define Hn  16
#define Mrows (Bn*SQn)   // 8192
#define Kdim 1024

// ---------------------------------------------------------------------------
// Scratch (static device globals — no dynamic allocation allowed)
// ---------------------------------------------------------------------------
__device__ __half g_hq[Bn*SQn*Dn];
__device__ __half g_hk[Bn*SKn*Dn];
__device__ __half g_hv[Bn*SKn*Dn];
__device__ __half g_wq[Dn*Dn];
__device__ __half g_wk[Dn*Dn];
__device__ __half g_wv[Dn*Dn];
__device__ __half g_wo[Dn*Dn];
__device__ __half g_q16[Bn*SQn*Dn];
__device__ __half g_k16[Bn*SKn*Dn];
__device__ __half g_v16[Bn*SKn*Dn];
__device__ __half g_attn[Bn*SQn*Dn];

// ---------------------------------------------------------------------------
// Helpers
// ---------------------------------------------------------------------------
__device__ __forceinline__ void cp_async16(void* s, const void* g) {
    unsigned sa = (unsigned)__cvta_generic_to_shared(s);
    asm volatile("cp.async.cg.shared.global [%0], [%1], 16;\n" :: "r"(sa), "l"(g));
}
__device__ __forceinline__ void cp_async16_s(unsigned s, const void* g) {
    asm volatile("cp.async.cg.shared.global [%0], [%1], 16;\n" :: "r"(s), "l"(g));
}
__device__ __forceinline__ void cp_commit() {
    asm volatile("cp.async.commit_group;\n");
}
template<int N> __device__ __forceinline__ void cp_wait() {
    asm volatile("cp.async.wait_group %0;\n" :: "n"(N));
}

// D = A(16x16,row) @ B(16x8,col) + D, f16 in / f32 accum
__device__ __forceinline__ void mma16816(float* c, const unsigned* a, unsigned b0, unsigned b1) {
    asm volatile(
        "mma.sync.aligned.m16n8k16.row.col.f32.f16.f16.f32 "
        "{%0,%1,%2,%3},{%4,%5,%6,%7},{%8,%9},{%0,%1,%2,%3};"
        : "+f"(c[0]), "+f"(c[1]), "+f"(c[2]), "+f"(c[3])
        : "r"(a[0]), "r"(a[1]), "r"(a[2]), "r"(a[3]), "r"(b0), "r"(b1));
}
// zero-C variant (starts a fresh accumulation)
__device__ __forceinline__ void mma16816_zc(float* c, const unsigned* a, unsigned b0, unsigned b1) {
    asm volatile(
        "mma.sync.aligned.m16n8k16.row.col.f32.f16.f16.f32 "
        "{%0,%1,%2,%3},{%4,%5,%6,%7},{%8,%9},{%10,%10,%10,%10};"
        : "=f"(c[0]), "=f"(c[1]), "=f"(c[2]), "=f"(c[3])
        : "r"(a[0]), "r"(a[1]), "r"(a[2]), "r"(a[3]), "r"(b0), "r"(b1), "f"(0.0f));
}

__device__ __forceinline__ void ldsm_x4(unsigned& r0, unsigned& r1, unsigned& r2,
                                        unsigned& r3, unsigned addr) {
    asm volatile(
        "ldmatrix.sync.aligned.m8n8.x4.shared.b16 {%0,%1,%2,%3}, [%4];"
        : "=r"(r0), "=r"(r1), "=r"(r2), "=r"(r3) : "r"(addr));
}
__device__ __forceinline__ void ldsm_x4_trans(unsigned& r0, unsigned& r1, unsigned& r2,
                                              unsigned& r3, unsigned addr) {
    asm volatile(
        "ldmatrix.sync.aligned.m8n8.x4.trans.shared.b16 {%0,%1,%2,%3}, [%4];"
        : "=r"(r0), "=r"(r1), "=r"(r2), "=r"(r3) : "r"(addr));
}

// SW128 swizzle for 128-byte rows: byte cb within row r
__device__ __forceinline__ unsigned sw_off(int r, int cb) {
    return (unsigned)(r * 128 + (cb ^ ((r & 7) << 4)));
}

// ---------------------------------------------------------------------------
// fp32 -> fp16 conversion, fused multi-array (z selects array), MLP 4
// ---------------------------------------------------------------------------
__global__ void f2h3_kernel(const float4* __restrict__ x0, const float4* __restrict__ x1,
                            const float4* __restrict__ x2,
                            __half2* __restrict__ y0, __half2* __restrict__ y1,
                            __half2* __restrict__ y2, int n4) {
    const float4* x = (blockIdx.z == 0) ? x0 : (blockIdx.z == 1) ? x1 : x2;
    __half2*      y = (blockIdx.z == 0) ? y0 : (blockIdx.z == 1) ? y1 : y2;
    int i = blockIdx.x * (blockDim.x * 4) + threadIdx.x;
#pragma unroll
    for (int u = 0; u < 4; ++u, i += blockDim.x) {
        if (i < n4) {
            float4 v = x[i];
            y[2*i]   = __floats2half2_rn(v.x, v.y);
            y[2*i+1] = __floats2half2_rn(v.z, v.w);
        }
    }
}

__global__ void f2h4_kernel(const float4* __restrict__ x0, const float4* __restrict__ x1,
                            const float4* __restrict__ x2, const float4* __restrict__ x3,
                            __half2* __restrict__ y0, __half2* __restrict__ y1,
                            __half2* __restrict__ y2, __half2* __restrict__ y3, int n4) {
    const float4* x = (blockIdx.z == 0) ? x0 : (blockIdx.z == 1) ? x1
                    : (blockIdx.z == 2) ? x2 : x3;
    __half2*      y = (blockIdx.z == 0) ? y0 : (blockIdx.z == 1) ? y1
                    : (blockIdx.z == 2) ? y2 : y3;
    int i = blockIdx.x * (blockDim.x * 4) + threadIdx.x;
#pragma unroll
    for (int u = 0; u < 4; ++u, i += blockDim.x) {
        if (i < n4) {
            float4 v = x[i];
            y[2*i]   = __floats2half2_rn(v.x, v.y);
            y[2*i+1] = __floats2half2_rn(v.z, v.w);
        }
    }
}

// ---------------------------------------------------------------------------
// GEMM core (proven): C[M,N] = A[M,K] @ W[N,K]^T + bias[N]
// Block 128x256, K-tile 64, 2-stage cp.async. 8 warps (2x4), warp tile 64x64.
// ---------------------------------------------------------------------------
#define GBM 128
#define GBN 256
#define GBK 64
#define GLD 72
#define ASTG (GBM * GLD)
#define BSTG (GBN * GLD)
#define GSMEM (2 * (ASTG + BSTG) * 2)          // 110592 bytes

template<bool HALF_OUT>
__device__ __forceinline__
void gemm_body(const __half* __restrict__ A, const __half* __restrict__ W,
               const float* __restrict__ bias, void* __restrict__ Cout,
               int M, int N, int K, char* gsm)
{
    __half* As = (__half*)gsm;
    __half* Bs = As + 2 * ASTG;

    const int tid  = threadIdx.x;
    const int warp = tid >> 5;
    const int lane = tid & 31;
    const int wr   = warp >> 2;
    const int wc   = warp & 3;
    const int bm   = blockIdx.y * GBM;
    const int bn   = blockIdx.x * GBN;

    wmma::fragment<wmma::accumulator, 16, 16, 16, float> acc[4][4];
#pragma unroll
    for (int i = 0; i < 4; i++)
#pragma unroll
        for (int j = 0; j < 4; j++) wmma::fill_fragment(acc[i][j], 0.0f);

    auto load_stage = [&](int bufi, int k0) {
#pragma unroll
        for (int it = 0; it < 4; ++it) {
            int idx = tid + it * 256;
            int r = idx >> 3, c = (idx & 7) * 8;
            cp_async16(&As[bufi * ASTG + r * GLD + c],
                       &A[(size_t)(bm + r) * K + k0 + c]);
        }
#pragma unroll
        for (int it = 0; it < 8; ++it) {
            int idx = tid + it * 256;
            int r = idx >> 3, c = (idx & 7) * 8;
            cp_async16(&Bs[bufi * BSTG + r * GLD + c],
                       &W[(size_t)(bn + r) * K + k0 + c]);
        }
        cp_commit();
    };

    load_stage(0, 0);
    int buf = 0;
    for (int k0 = 0; k0 < K; k0 += GBK) {
        bool more = (k0 + GBK) < K;
        if (more) {
            load_stage(buf ^ 1, k0 + GBK);
            cp_wait<1>();
        } else {
            cp_wait<0>();
        }
        __syncthreads();

        const __half* Ab = As + buf * ASTG;
        const __half* Bb = Bs + buf * BSTG;
#pragma unroll
        for (int kk = 0; kk < GBK; kk += 16) {
            wmma::fragment<wmma::matrix_a, 16, 16, 16, half, wmma::row_major> af[4];
            wmma::fragment<wmma::matrix_b, 16, 16, 16, half, wmma::col_major> bf[4];
#pragma unroll
            for (int i = 0; i < 4; i++)
                wmma::load_matrix_sync(af[i], &Ab[(wr*64 + i*16) * GLD + kk], GLD);
#pragma unroll
            for (int j = 0; j < 4; j++)
                wmma::load_matrix_sync(bf[j], &Bb[(wc*64 + j*16) * GLD + kk], GLD);
#pragma unroll
            for (int i = 0; i < 4; i++)
#pragma unroll
                for (int j = 0; j < 4; j++)
                    wmma::mma_sync(acc[i][j], af[i], bf[j], acc[i][j]);
        }
        __syncthreads();
        buf ^= 1;
    }

    // Epilogue
    float* stage = (float*)gsm + warp * 256;
#pragma unroll
    for (int i = 0; i < 4; i++) {
#pragma unroll
        for (int j = 0; j < 4; j++) {
            wmma::store_matrix_sync(stage, acc[i][j], 16, wmma::mem_row_major);
            __syncwarp();
            int row0 = bm + wr*64 + i*16;
            int col0 = bn + wc*64 + j*16;
#pragma unroll
            for (int e = lane; e < 256; e += 32) {
                int rr = e >> 4, c2 = e & 15;
                float v = stage[rr * 16 + c2] + bias[col0 + c2];
                if (HALF_OUT)
                    ((__half*)Cout)[(size_t)(row0 + rr) * N + col0 + c2] = __float2half(v);
                else
                    ((float*)Cout)[(size_t)(row0 + rr) * N + col0 + c2] = v;
            }
            __syncwarp();
        }
    }
}

__global__ __launch_bounds__(256, 1)
void gemm_qkv(const __half* __restrict__ Aq, const __half* __restrict__ Ak,
              const __half* __restrict__ Av,
              const __half* __restrict__ Wq, const __half* __restrict__ Wk,
              const __half* __restrict__ Wv,
              const float* __restrict__ bq, const float* __restrict__ bk,
              const float* __restrict__ bv,
              __half* __restrict__ Cq, __half* __restrict__ Ck,
              __half* __restrict__ Cv)
{
    extern __shared__ char gsm[];
    const __half* A; const __half* W; const float* bias; __half* C;
    if (blockIdx.z == 0)      { A = Aq; W = Wq; bias = bq; C = Cq; }
    else if (blockIdx.z == 1) { A = Ak; W = Wk; bias = bk; C = Ck; }
    else                      { A = Av; W = Wv; bias = bv; C = Cv; }
    gemm_body<true>(A, W, bias, C, Mrows, Dn, Kdim, gsm);
}

__global__ __launch_bounds__(256, 1)
void gemm_out(const __half* __restrict__ A, const __half* __restrict__ W,
              const float* __restrict__ bias, float* __restrict__ C)
{
    extern __shared__ char gsm[];
    gemm_body<false>(A, W, bias, C, Mrows, Dn, Kdim, gsm);
}

// ---------------------------------------------------------------------------
// Flash attention v3.1: pipelined 3-buffer K/V ring, ONE __syncthreads per
// k-tile, QK(kt+1) interleaved with PV(kt), SW128-swizzled smem (48 KB),
// Q fragments straight from gmem. CTA = 64 q-rows (4 warps x 16).
// R12: regs pinned to 128 (4 CTAs/SM) + heavy-tiles-first scheduling.
// ---------------------------------------------------------------------------
#define KVBUF 8192                 // bytes per 64x64 f16 tile (swizzled, 128B rows)
#define ATT_SMEM (6 * KVBUF)       // 3 K buffers + 3 V buffers = 48 KB

__global__ __launch_bounds__(128, 4)
void attn_kernel(const __half* __restrict__ Q, const __half* __restrict__ Kg,
                 const __half* __restrict__ Vg,
                 const unsigned char* __restrict__ kpm, __half* __restrict__ Out)
{
    extern __shared__ char asmem[];
    const unsigned ksaddr = (unsigned)__cvta_generic_to_shared(asmem);
    const unsigned vsaddr = ksaddr + 3 * KVBUF;

    // Heavy-first: largest qt (most k-tiles) scheduled earliest -> better tail.
    const int qt = (int)gridDim.x - 1 - (int)blockIdx.x;
    const int h = blockIdx.y, b = blockIdx.z;
    const int q0 = qt * 64;
    const int tid = threadIdx.x, warp = tid >> 5, lane = tid & 31;
    const int gr = lane >> 2, qd = lane & 3;
    const float scl2 = 0.125f * 1.4426950408889634f;   // scale * log2(e)

    // ldmatrix lane selectors (row&7 == lane&7 for all -> shared swizzle mask)
    const unsigned xm = (unsigned)((lane & 7) << 4);
    const int krow_sel = (lane & 7) + ((lane & 16) ? 8 : 0);
    const int vrow_sel = lane & 15;
    unsigned koff[4], voff[4];
#pragma unroll
    for (int i = 0; i < 4; ++i) {
        koff[i] = (unsigned)(i * 32 + ((lane & 8)  ? 16 : 0)) ^ xm;
        voff[i] = (unsigned)(i * 32 + ((lane & 16) ? 16 : 0)) ^ xm;
    }
    const unsigned krow_b = (unsigned)(krow_sel * 128);
    const unsigned vrow_b = (unsigned)(vrow_sel * 128);

    // ---- issue first K/V loads ----
    auto load_kv = [&](int bufi, int kt) {
        const int k0 = kt * 64;
#pragma unroll
        for (int it = 0; it < 4; ++it) {
            int id = tid + it * 128;
            int r = id >> 3, chb = (id & 7) * 16;
            unsigned so = sw_off(r, chb) + (unsigned)(bufi * KVBUF);
            size_t gi = ((size_t)b * SKn + k0 + r) * Dn + h * 64 + (id & 7) * 8;
            cp_async16_s(ksaddr + so, &Kg[gi]);
            cp_async16_s(vsaddr + so, &Vg[gi]);
        }
        cp_commit();
    };

    load_kv(0, 0);
    if (qt >= 1) load_kv(1, 1);

    // ---- Q A-fragments straight from gmem (L2-hot; once per block) ----
    const int wrow = warp * 16 + gr;
    const int row_g0 = q0 + wrow;
    unsigned aQ[4][4];
    {
        const __half* qrow0 = Q + ((size_t)b * SQn + row_g0) * Dn + h * 64;
        const __half* qrow1 = qrow0 + 8 * (size_t)Dn;
#pragma unroll
        for (int kk = 0; kk < 4; ++kk) {
            int cb = kk * 16 + qd * 2;
            aQ[kk][0] = *(const unsigned*)&qrow0[cb];
            aQ[kk][1] = *(const unsigned*)&qrow1[cb];
            aQ[kk][2] = *(const unsigned*)&qrow0[cb + 8];
            aQ[kk][3] = *(const unsigned*)&qrow1[cb + 8];
        }
    }

    float o[8][4];
#pragma unroll
    for (int j = 0; j < 8; j++)
#pragma unroll
        for (int e = 0; e < 4; e++) o[j][e] = 0.0f;
    float m0 = -1e30f, m1 = -1e30f, l0 = 0.0f, l1 = 0.0f;

    float s[8][4];

    // QK for one tile: ldmatrix K fragments + mma into s (zero-start)
    auto qk_tile = [&](int bufi) {
        const unsigned kb = ksaddr + (unsigned)(bufi * KVBUF) + krow_b;
#pragma unroll
        for (int jp = 0; jp < 4; ++jp) {
            const unsigned rowb = kb + (unsigned)(jp * 2048);
#pragma unroll
            for (int kk = 0; kk < 4; ++kk) {
                unsigned r0, r1, r2, r3;
                ldsm_x4(r0, r1, r2, r3, rowb + koff[kk]);
                if (kk == 0) {
                    mma16816_zc(s[2*jp],     aQ[0], r0, r1);
                    mma16816_zc(s[2*jp + 1], aQ[0], r2, r3);
                } else {
                    mma16816(s[2*jp],     aQ[kk], r0, r1);
                    mma16816(s[2*jp + 1], aQ[kk], r2, r3);
                }
            }
        }
    };

    // prologue: tile 0 scores
    cp_wait<0>();
    __syncthreads();
    qk_tile(0);

    for (int kt = 0; kt <= qt; ++kt) {
        const int k0 = kt * 64;

        // ---- online softmax on s (tile kt) ----
        const unsigned char* kb = kpm + (size_t)b * SKn + k0;
        float mx0 = -1e30f, mx1 = -1e30f;
        if (kt == qt) {
#pragma unroll
            for (int j = 0; j < 8; ++j) {
                int cbase = j * 8 + qd * 2;
                uchar2 pb = *(const uchar2*)&kb[cbase];
                float pen0 = pb.x ? -1e30f : 0.0f;
                float pen1 = pb.y ? -1e30f : 0.0f;
                float v0 = s[j][0] * scl2 + pen0;
                float v1 = s[j][1] * scl2 + pen1;
                float v2 = s[j][2] * scl2 + pen0;
                float v3 = s[j][3] * scl2 + pen1;
                int c0 = k0 + cbase, c1 = c0 + 1;
                if (c0 > row_g0)     v0 = -1e30f;
                if (c1 > row_g0)     v1 = -1e30f;
                if (c0 > row_g0 + 8) v2 = -1e30f;
                if (c1 > row_g0 + 8) v3 = -1e30f;
                s[j][0] = v0; s[j][1] = v1; s[j][2] = v2; s[j][3] = v3;
                mx0 = fmaxf(mx0, fmaxf(v0, v1));
                mx1 = fmaxf(mx1, fmaxf(v2, v3));
            }
        } else {
#pragma unroll
            for (int j = 0; j < 8; ++j) {
                int cbase = j * 8 + qd * 2;
                uchar2 pb = *(const uchar2*)&kb[cbase];
                float pen0 = pb.x ? -1e30f : 0.0f;
                float pen1 = pb.y ? -1e30f : 0.0f;
                float v0 = s[j][0] * scl2 + pen0;
                float v1 = s[j][1] * scl2 + pen1;
                float v2 = s[j][2] * scl2 + pen0;
                float v3 = s[j][3] * scl2 + pen1;
                s[j][0] = v0; s[j][1] = v1; s[j][2] = v2; s[j][3] = v3;
                mx0 = fmaxf(mx0, fmaxf(v0, v1));
                mx1 = fmaxf(mx1, fmaxf(v2, v3));
            }
        }
        mx0 = fmaxf(mx0, __shfl_xor_sync(0xffffffffu, mx0, 1));
        mx0 = fmaxf(mx0, __shfl_xor_sync(0xffffffffu, mx0, 2));
        mx1 = fmaxf(mx1, __shfl_xor_sync(0xffffffffu, mx1, 1));
        mx1 = fmaxf(mx1, __shfl_xor_sync(0xffffffffu, mx1, 2));

        float mn0 = fmaxf(m0, mx0), mn1 = fmaxf(m1, mx1);
        float corr0 = exp2f(m0 - mn0), corr1 = exp2f(m1 - mn1);
        float sum0 = 0.0f, sum1 = 0.0f;
#pragma unroll
        for (int j = 0; j < 8; ++j) {
            s[j][0] = exp2f(s[j][0] - mn0);
            s[j][1] = exp2f(s[j][1] - mn0);
            s[j][2] = exp2f(s[j][2] - mn1);
            s[j][3] = exp2f(s[j][3] - mn1);
            sum0 += s[j][0] + s[j][1];
            sum1 += s[j][2] + s[j][3];
        }
        sum0 += __shfl_xor_sync(0xffffffffu, sum0, 1);
        sum0 += __shfl_xor_sync(0xffffffffu, sum0, 2);
        sum1 += __shfl_xor_sync(0xffffffffu, sum1, 1);
        sum1 += __shfl_xor_sync(0xffffffffu, sum1, 2);
        l0 = l0 * corr0 + sum0;  m0 = mn0;
        l1 = l1 * corr1 + sum1;  m1 = mn1;

#pragma unroll
        for (int j = 0; j < 8; ++j) {
            o[j][0] *= corr0; o[j][1] *= corr0;
            o[j][2] *= corr1; o[j][3] *= corr1;
        }

        // P (fp16) A-fragments — register repack (s dead afterwards)
        unsigned aP[4][4];
#pragma unroll
        for (int kk = 0; kk < 4; ++kk) {
            __half2 h0 = __floats2half2_rn(s[2*kk][0],   s[2*kk][1]);
            __half2 h1 = __floats2half2_rn(s[2*kk][2],   s[2*kk][3]);
            __half2 h2 = __floats2half2_rn(s[2*kk+1][0], s[2*kk+1][1]);
            __half2 h3 = __floats2half2_rn(s[2*kk+1][2], s[2*kk+1][3]);
            aP[kk][0] = *(unsigned*)&h0;
            aP[kk][1] = *(unsigned*)&h1;
            aP[kk][2] = *(unsigned*)&h2;
            aP[kk][3] = *(unsigned*)&h3;
        }

        // ---- pipeline turn: make tile kt+1 ready, prefetch kt+2, QK(kt+1) ----
        if (kt < qt) {
            cp_wait<0>();          // load(kt+1) done (issued a full iter ago)
            __syncthreads();       // visibility + all warps past tile kt-1 use
            if (kt + 2 <= qt) load_kv((kt + 2) % 3, kt + 2);
            qk_tile((kt + 1) % 3); // overlaps with PV below
        }

        // ---- O += P @ V (tile kt) ----
        const unsigned vb = vsaddr + (unsigned)((kt % 3) * KVBUF) + vrow_b;
#pragma unroll
        for (int kk = 0; kk < 4; ++kk) {
            const unsigned rowb = vb + (unsigned)(kk * 2048);
#pragma unroll
            for (int jp = 0; jp < 4; ++jp) {
                unsigned d0, d1, d2, d3;
                ldsm_x4_trans(d0, d1, d2, d3, rowb + voff[jp]);
                mma16816(o[2*jp],     aP[kk], d0, d1);
                mma16816(o[2*jp + 1], aP[kk], d2, d3);
            }
        }
    }

    // ---- normalize + write out ----
    float inv0 = 1.0f / l0, inv1 = 1.0f / l1;
    const size_t orow0 = ((size_t)b * SQn + row_g0) * Dn + h * 64;
    const size_t orow1 = orow0 + 8 * (size_t)Dn;
#pragma unroll
    for (int j = 0; j < 8; ++j) {
        __half2 w0 = __floats2half2_rn(o[j][0] * inv0, o[j][1] * inv0);
        __half2 w1 = __floats2half2_rn(o[j][2] * inv1, o[j][3] * inv1);
        *(__half2*)&Out[orow0 + j*8 + qd*2] = w0;
        *(__half2*)&Out[orow1 + j*8 + qd*2] = w1;
    }
}

// ---------------------------------------------------------------------------
// Launch
// ---------------------------------------------------------------------------
extern "C" void kernel_launch(void* const* d_in, const int* in_sizes, int n_in,
                              void* d_out, int out_size)
{
    const float* query = (const float*)d_in[0];
    const float* key   = (const float*)d_in[1];
    const float* value = (const float*)d_in[2];
    // d_in[3] = attn_mask (causal) — applied analytically in attn_kernel
    const unsigned char* kpm = (const unsigned char*)d_in[4];
    const float* Wq = (const float*)d_in[5];
    const float* bq = (const float*)d_in[6];
    const float* Wk = (const float*)d_in[7];
    const float* bk = (const float*)d_in[8];
    const float* Wv = (const float*)d_in[9];
    const float* bv = (const float*)d_in[10];
    const float* Wo = (const float*)d_in[11];
    const float* bo = (const float*)d_in[12];

    void *p_hq, *p_hk, *p_hv, *p_wq, *p_wk, *p_wv, *p_wo;
    void *p_q16, *p_k16, *p_v16, *p_attn;
    cudaGetSymbolAddress(&p_hq, g_hq);
    cudaGetSymbolAddress(&p_hk, g_hk);
    cudaGetSymbolAddress(&p_hv, g_hv);
    cudaGetSymbolAddress(&p_wq, g_wq);
    cudaGetSymbolAddress(&p_wk, g_wk);
    cudaGetSymbolAddress(&p_wv, g_wv);
    cudaGetSymbolAddress(&p_wo, g_wo);
    cudaGetSymbolAddress(&p_q16, g_q16);
    cudaGetSymbolAddress(&p_k16, g_k16);
    cudaGetSymbolAddress(&p_v16, g_v16);
    cudaGetSymbolAddress(&p_attn, g_attn);

    const int n4in = Bn * SQn * Dn / 4;
    const int n4w  = Dn * Dn / 4;
    const int tpb = 256, vpb = tpb * 4;

    dim3 fin_grid((n4in + vpb - 1) / vpb, 1, 3);
    f2h3_kernel<<<fin_grid, tpb>>>(
        (const float4*)query, (const float4*)key, (const float4*)value,
        (__half2*)p_hq, (__half2*)p_hk, (__half2*)p_hv, n4in);

    dim3 fw_grid((n4w + vpb - 1) / vpb, 1, 4);
    f2h4_kernel<<<fw_grid, tpb>>>(
        (const float4*)Wq, (const float4*)Wk, (const float4*)Wv, (const float4*)Wo,
        (__half2*)p_wq, (__half2*)p_wk, (__half2*)p_wv, (__half2*)p_wo, n4w);

    cudaFuncSetAttribute(gemm_qkv, cudaFuncAttributeMaxDynamicSharedMemorySize, GSMEM);
    cudaFuncSetAttribute(gemm_out, cudaFuncAttributeMaxDynamicSharedMemorySize, GSMEM);
    cudaFuncSetAttribute(attn_kernel, cudaFuncAttributeMaxDynamicSharedMemorySize, ATT_SMEM);

    dim3 qkv_grid(Dn / GBN, Mrows / GBM, 3);   // (4, 64, 3) = 768 CTAs
    gemm_qkv<<<qkv_grid, 256, GSMEM>>>(
        (const __half*)p_hq, (const __half*)p_hk, (const __half*)p_hv,
        (const __half*)p_wq, (const __half*)p_wk, (const __half*)p_wv,
        bq, bk, bv,
        (__half*)p_q16, (__half*)p_k16, (__half*)p_v16);

    attn_kernel<<<dim3(SQn / 64, Hn, Bn), 128, ATT_SMEM>>>(
        (const __half*)p_q16, (const __half*)p_k16, (const __half*)p_v16,
        kpm, (__half*)p_attn);

    dim3 ogrid(Dn / GBN, Mrows / GBM, 1);      // (4, 64)
    gemm_out<<<ogrid, 256, GSMEM>>>(
        (const __half*)p_attn, (const __half*)p_wo, bo, (float*)d_out);
}

// round 15
// speedup vs baseline: 1.0201x; 1.0201x over previous
#include <cuda_runtime.h>
#include <cuda_fp16.h>
#include <mma.h>
#include <cstdint>

using namespace nvcuda;

// Problem constants
#define Bn  4
#define SQn 2048
#define SKn 2048
#define Dn  1024
#define Hn  16
#define Mrows (Bn*SQn)   // 8192
#define Kdim 1024

// ---------------------------------------------------------------------------
// Scratch (static device globals — no dynamic allocation allowed)
// ---------------------------------------------------------------------------
__device__ __half g_hq[Bn*SQn*Dn];
__device__ __half g_hk[Bn*SKn*Dn];
__device__ __half g_hv[Bn*SKn*Dn];
__device__ __half g_wq[Dn*Dn];
__device__ __half g_wk[Dn*Dn];
__device__ __half g_wv[Dn*Dn];
__device__ __half g_wo[Dn*Dn];
__device__ __half g_q16[Bn*SQn*Dn];
__device__ __half g_k16[Bn*SKn*Dn];
__device__ __half g_v16[Bn*SKn*Dn];
__device__ __half g_attn[Bn*SQn*Dn];

// ---------------------------------------------------------------------------
// Helpers
// ---------------------------------------------------------------------------
__device__ __forceinline__ void cp_async16(void* s, const void* g) {
    unsigned sa = (unsigned)__cvta_generic_to_shared(s);
    asm volatile("cp.async.cg.shared.global [%0], [%1], 16;\n" :: "r"(sa), "l"(g));
}
__device__ __forceinline__ void cp_async16_s(unsigned s, const void* g) {
    asm volatile("cp.async.cg.shared.global [%0], [%1], 16;\n" :: "r"(s), "l"(g));
}
__device__ __forceinline__ void cp_commit() {
    asm volatile("cp.async.commit_group;\n");
}
template<int N> __device__ __forceinline__ void cp_wait() {
    asm volatile("cp.async.wait_group %0;\n" :: "n"(N));
}

// D = A(16x16,row) @ B(16x8,col) + D, f16 in / f32 accum
__device__ __forceinline__ void mma16816(float* c, const unsigned* a, unsigned b0, unsigned b1) {
    asm volatile(
        "mma.sync.aligned.m16n8k16.row.col.f32.f16.f16.f32 "
        "{%0,%1,%2,%3},{%4,%5,%6,%7},{%8,%9},{%0,%1,%2,%3};"
        : "+f"(c[0]), "+f"(c[1]), "+f"(c[2]), "+f"(c[3])
        : "r"(a[0]), "r"(a[1]), "r"(a[2]), "r"(a[3]), "r"(b0), "r"(b1));
}
// zero-C variant (starts a fresh accumulation)
__device__ __forceinline__ void mma16816_zc(float* c, const unsigned* a, unsigned b0, unsigned b1) {
    asm volatile(
        "mma.sync.aligned.m16n8k16.row.col.f32.f16.f16.f32 "
        "{%0,%1,%2,%3},{%4,%5,%6,%7},{%8,%9},{%10,%10,%10,%10};"
        : "=f"(c[0]), "=f"(c[1]), "=f"(c[2]), "=f"(c[3])
        : "r"(a[0]), "r"(a[1]), "r"(a[2]), "r"(a[3]), "r"(b0), "r"(b1), "f"(0.0f));
}

__device__ __forceinline__ void ldsm_x4(unsigned& r0, unsigned& r1, unsigned& r2,
                                        unsigned& r3, unsigned addr) {
    asm volatile(
        "ldmatrix.sync.aligned.m8n8.x4.shared.b16 {%0,%1,%2,%3}, [%4];"
        : "=r"(r0), "=r"(r1), "=r"(r2), "=r"(r3) : "r"(addr));
}
__device__ __forceinline__ void ldsm_x4_trans(unsigned& r0, unsigned& r1, unsigned& r2,
                                              unsigned& r3, unsigned addr) {
    asm volatile(
        "ldmatrix.sync.aligned.m8n8.x4.trans.shared.b16 {%0,%1,%2,%3}, [%4];"
        : "=r"(r0), "=r"(r1), "=r"(r2), "=r"(r3) : "r"(addr));
}

// SW128 swizzle for 128-byte rows: byte cb within row r
__device__ __forceinline__ unsigned sw_off(int r, int cb) {
    return (unsigned)(r * 128 + (cb ^ ((r & 7) << 4)));
}

// ---------------------------------------------------------------------------
// fp32 -> fp16 conversion, fused multi-array (z selects array), MLP 4
// ---------------------------------------------------------------------------
__global__ void f2h3_kernel(const float4* __restrict__ x0, const float4* __restrict__ x1,
                            const float4* __restrict__ x2,
                            __half2* __restrict__ y0, __half2* __restrict__ y1,
                            __half2* __restrict__ y2, int n4) {
    const float4* x = (blockIdx.z == 0) ? x0 : (blockIdx.z == 1) ? x1 : x2;
    __half2*      y = (blockIdx.z == 0) ? y0 : (blockIdx.z == 1) ? y1 : y2;
    int i = blockIdx.x * (blockDim.x * 4) + threadIdx.x;
#pragma unroll
    for (int u = 0; u < 4; ++u, i += blockDim.x) {
        if (i < n4) {
            float4 v = x[i];
            y[2*i]   = __floats2half2_rn(v.x, v.y);
            y[2*i+1] = __floats2half2_rn(v.z, v.w);
        }
    }
}

__global__ void f2h4_kernel(const float4* __restrict__ x0, const float4* __restrict__ x1,
                            const float4* __restrict__ x2, const float4* __restrict__ x3,
                            __half2* __restrict__ y0, __half2* __restrict__ y1,
                            __half2* __restrict__ y2, __half2* __restrict__ y3, int n4) {
    const float4* x = (blockIdx.z == 0) ? x0 : (blockIdx.z == 1) ? x1
                    : (blockIdx.z == 2) ? x2 : x3;
    __half2*      y = (blockIdx.z == 0) ? y0 : (blockIdx.z == 1) ? y1
                    : (blockIdx.z == 2) ? y2 : y3;
    int i = blockIdx.x * (blockDim.x * 4) + threadIdx.x;
#pragma unroll
    for (int u = 0; u < 4; ++u, i += blockDim.x) {
        if (i < n4) {
            float4 v = x[i];
            y[2*i]   = __floats2half2_rn(v.x, v.y);
            y[2*i+1] = __floats2half2_rn(v.z, v.w);
        }
    }
}

// ---------------------------------------------------------------------------
// GEMM core: C[M,N] = A[M,K] @ W[N,K]^T + bias[N]
// Block 128x256, K-tile 64, 2-stage cp.async. 8 warps (2x4), warp tile 64x64.
// R15: panel epilogue (16x64 staged, coalesced half2/float2 stores).
// ---------------------------------------------------------------------------
#define GBM 128
#define GBN 256
#define GBK 64
#define GLD 72
#define ASTG (GBM * GLD)
#define BSTG (GBN * GLD)
#define GSMEM (2 * (ASTG + BSTG) * 2)          // 110592 bytes

template<bool HALF_OUT>
__device__ __forceinline__
void gemm_body(const __half* __restrict__ A, const __half* __restrict__ W,
               const float* __restrict__ bias, void* __restrict__ Cout,
               int M, int N, int K, char* gsm)
{
    __half* As = (__half*)gsm;
    __half* Bs = As + 2 * ASTG;

    const int tid  = threadIdx.x;
    const int warp = tid >> 5;
    const int lane = tid & 31;
    const int wr   = warp >> 2;
    const int wc   = warp & 3;
    const int bm   = blockIdx.y * GBM;
    const int bn   = blockIdx.x * GBN;

    wmma::fragment<wmma::accumulator, 16, 16, 16, float> acc[4][4];
#pragma unroll
    for (int i = 0; i < 4; i++)
#pragma unroll
        for (int j = 0; j < 4; j++) wmma::fill_fragment(acc[i][j], 0.0f);

    auto load_stage = [&](int bufi, int k0) {
#pragma unroll
        for (int it = 0; it < 4; ++it) {
            int idx = tid + it * 256;
            int r = idx >> 3, c = (idx & 7) * 8;
            cp_async16(&As[bufi * ASTG + r * GLD + c],
                       &A[(size_t)(bm + r) * K + k0 + c]);
        }
#pragma unroll
        for (int it = 0; it < 8; ++it) {
            int idx = tid + it * 256;
            int r = idx >> 3, c = (idx & 7) * 8;
            cp_async16(&Bs[bufi * BSTG + r * GLD + c],
                       &W[(size_t)(bn + r) * K + k0 + c]);
        }
        cp_commit();
    };

    load_stage(0, 0);
    int buf = 0;
    for (int k0 = 0; k0 < K; k0 += GBK) {
        bool more = (k0 + GBK) < K;
        if (more) {
            load_stage(buf ^ 1, k0 + GBK);
            cp_wait<1>();
        } else {
            cp_wait<0>();
        }
        __syncthreads();

        const __half* Ab = As + buf * ASTG;
        const __half* Bb = Bs + buf * BSTG;
#pragma unroll
        for (int kk = 0; kk < GBK; kk += 16) {
            wmma::fragment<wmma::matrix_a, 16, 16, 16, half, wmma::row_major> af[4];
            wmma::fragment<wmma::matrix_b, 16, 16, 16, half, wmma::col_major> bf[4];
#pragma unroll
            for (int i = 0; i < 4; i++)
                wmma::load_matrix_sync(af[i], &Ab[(wr*64 + i*16) * GLD + kk], GLD);
#pragma unroll
            for (int j = 0; j < 4; j++)
                wmma::load_matrix_sync(bf[j], &Bb[(wc*64 + j*16) * GLD + kk], GLD);
#pragma unroll
            for (int i = 0; i < 4; i++)
#pragma unroll
                for (int j = 0; j < 4; j++)
                    wmma::mma_sync(acc[i][j], af[i], bf[j], acc[i][j]);
        }
        __syncthreads();
        buf ^= 1;
    }

    // Panel epilogue: per warp, 4 row-panels of 16x64 staged through smem,
    // then coalesced half2/float2 stores with bias.
    float* stage = (float*)gsm + warp * 16 * 68;    // 16x68 floats per warp
#pragma unroll
    for (int i = 0; i < 4; i++) {
#pragma unroll
        for (int j = 0; j < 4; j++)
            wmma::store_matrix_sync(&stage[j * 16], acc[i][j], 68, wmma::mem_row_major);
        __syncwarp();
        const int row0 = bm + wr*64 + i*16;
        const int col0 = bn + wc*64;
#pragma unroll
        for (int e = lane; e < 512; e += 32) {       // 16 rows x 32 col-pairs
            int rr = e >> 5, cp = e & 31;
            float v0 = stage[rr * 68 + 2*cp]     + bias[col0 + 2*cp];
            float v1 = stage[rr * 68 + 2*cp + 1] + bias[col0 + 2*cp + 1];
            if (HALF_OUT) {
                *(__half2*)&((__half*)Cout)[(size_t)(row0 + rr) * N + col0 + 2*cp] =
                    __floats2half2_rn(v0, v1);
            } else {
                float2 f2; f2.x = v0; f2.y = v1;
                *(float2*)&((float*)Cout)[(size_t)(row0 + rr) * N + col0 + 2*cp] = f2;
            }
        }
        __syncwarp();
    }
}

__global__ __launch_bounds__(256, 1)
void gemm_qkv(const __half* __restrict__ Aq, const __half* __restrict__ Ak,
              const __half* __restrict__ Av,
              const __half* __restrict__ Wq, const __half* __restrict__ Wk,
              const __half* __restrict__ Wv,
              const float* __restrict__ bq, const float* __restrict__ bk,
              const float* __restrict__ bv,
              __half* __restrict__ Cq, __half* __restrict__ Ck,
              __half* __restrict__ Cv)
{
    extern __shared__ char gsm[];
    const __half* A; const __half* W; const float* bias; __half* C;
    if (blockIdx.z == 0)      { A = Aq; W = Wq; bias = bq; C = Cq; }
    else if (blockIdx.z == 1) { A = Ak; W = Wk; bias = bk; C = Ck; }
    else                      { A = Av; W = Wv; bias = bv; C = Cv; }
    gemm_body<true>(A, W, bias, C, Mrows, Dn, Kdim, gsm);
}

__global__ __launch_bounds__(256, 1)
void gemm_out(const __half* __restrict__ A, const __half* __restrict__ W,
              const float* __restrict__ bias, float* __restrict__ C)
{
    extern __shared__ char gsm[];
    gemm_body<false>(A, W, bias, C, Mrows, Dn, Kdim, gsm);
}

// ---------------------------------------------------------------------------
// Flash attention v3 (R11-proven): pipelined 3-buffer K/V ring, ONE
// __syncthreads per k-tile, QK(kt+1) interleaved with PV(kt), SW128 smem,
// Q fragments from gmem. CTA = 64 q-rows. R15: heavy-tiles-first scheduling.
// ---------------------------------------------------------------------------
#define KVBUF 8192                 // bytes per 64x64 f16 tile (swizzled, 128B rows)
#define ATT_SMEM (6 * KVBUF)       // 3 K buffers + 3 V buffers = 48 KB

__global__ __launch_bounds__(128)
void attn_kernel(const __half* __restrict__ Q, const __half* __restrict__ Kg,
                 const __half* __restrict__ Vg,
                 const unsigned char* __restrict__ kpm, __half* __restrict__ Out)
{
    extern __shared__ char asmem[];
    const unsigned ksaddr = (unsigned)__cvta_generic_to_shared(asmem);
    const unsigned vsaddr = ksaddr + 3 * KVBUF;

    // Heavy-first: largest qt (most k-tiles) scheduled earliest -> better tail.
    const int qt = (int)gridDim.x - 1 - (int)blockIdx.x;
    const int h = blockIdx.y, b = blockIdx.z;
    const int q0 = qt * 64;
    const int tid = threadIdx.x, warp = tid >> 5, lane = tid & 31;
    const int gr = lane >> 2, qd = lane & 3;
    const float scl2 = 0.125f * 1.4426950408889634f;   // scale * log2(e)

    // ldmatrix lane selectors (row&7 == lane&7 for all -> shared swizzle mask)
    const unsigned xm = (unsigned)((lane & 7) << 4);
    const int krow_sel = (lane & 7) + ((lane & 16) ? 8 : 0);
    const int vrow_sel = lane & 15;
    unsigned koff[4], voff[4];
#pragma unroll
    for (int i = 0; i < 4; ++i) {
        koff[i] = (unsigned)(i * 32 + ((lane & 8)  ? 16 : 0)) ^ xm;
        voff[i] = (unsigned)(i * 32 + ((lane & 16) ? 16 : 0)) ^ xm;
    }
    const unsigned krow_b = (unsigned)(krow_sel * 128);
    const unsigned vrow_b = (unsigned)(vrow_sel * 128);

    // ---- issue first K/V loads ----
    auto load_kv = [&](int bufi, int kt) {
        const int k0 = kt * 64;
#pragma unroll
        for (int it = 0; it < 4; ++it) {
            int id = tid + it * 128;
            int r = id >> 3, chb = (id & 7) * 16;
            unsigned so = sw_off(r, chb) + (unsigned)(bufi * KVBUF);
            size_t gi = ((size_t)b * SKn + k0 + r) * Dn + h * 64 + (id & 7) * 8;
            cp_async16_s(ksaddr + so, &Kg[gi]);
            cp_async16_s(vsaddr + so, &Vg[gi]);
        }
        cp_commit();
    };

    load_kv(0, 0);
    if (qt >= 1) load_kv(1, 1);

    // ---- Q A-fragments straight from gmem (L2-hot; once per block) ----
    const int wrow = warp * 16 + gr;
    const int row_g0 = q0 + wrow;
    unsigned aQ[4][4];
    {
        const __half* qrow0 = Q + ((size_t)b * SQn + row_g0) * Dn + h * 64;
        const __half* qrow1 = qrow0 + 8 * (size_t)Dn;
#pragma unroll
        for (int kk = 0; kk < 4; ++kk) {
            int cb = kk * 16 + qd * 2;
            aQ[kk][0] = *(const unsigned*)&qrow0[cb];
            aQ[kk][1] = *(const unsigned*)&qrow1[cb];
            aQ[kk][2] = *(const unsigned*)&qrow0[cb + 8];
            aQ[kk][3] = *(const unsigned*)&qrow1[cb + 8];
        }
    }

    float o[8][4];
#pragma unroll
    for (int j = 0; j < 8; j++)
#pragma unroll
        for (int e = 0; e < 4; e++) o[j][e] = 0.0f;
    float m0 = -1e30f, m1 = -1e30f, l0 = 0.0f, l1 = 0.0f;

    float s[8][4];

    // QK for one tile: ldmatrix K fragments + mma into s (zero-start)
    auto qk_tile = [&](int bufi) {
        const unsigned kb = ksaddr + (unsigned)(bufi * KVBUF) + krow_b;
#pragma unroll
        for (int jp = 0; jp < 4; ++jp) {
            const unsigned rowb = kb + (unsigned)(jp * 2048);
#pragma unroll
            for (int kk = 0; kk < 4; ++kk) {
                unsigned r0, r1, r2, r3;
                ldsm_x4(r0, r1, r2, r3, rowb + koff[kk]);
                if (kk == 0) {
                    mma16816_zc(s[2*jp],     aQ[0], r0, r1);
                    mma16816_zc(s[2*jp + 1], aQ[0], r2, r3);
                } else {
                    mma16816(s[2*jp],     aQ[kk], r0, r1);
                    mma16816(s[2*jp + 1], aQ[kk], r2, r3);
                }
            }
        }
    };

    // prologue: tile 0 scores
    cp_wait<0>();
    __syncthreads();
    qk_tile(0);

    for (int kt = 0; kt <= qt; ++kt) {
        const int k0 = kt * 64;

        // ---- online softmax on s (tile kt) ----
        const unsigned char* kb = kpm + (size_t)b * SKn + k0;
        float mx0 = -1e30f, mx1 = -1e30f;
        if (kt == qt) {
#pragma unroll
            for (int j = 0; j < 8; ++j) {
                int cbase = j * 8 + qd * 2;
                uchar2 pb = *(const uchar2*)&kb[cbase];
                float pen0 = pb.x ? -1e30f : 0.0f;
                float pen1 = pb.y ? -1e30f : 0.0f;
                float v0 = s[j][0] * scl2 + pen0;
                float v1 = s[j][1] * scl2 + pen1;
                float v2 = s[j][2] * scl2 + pen0;
                float v3 = s[j][3] * scl2 + pen1;
                int c0 = k0 + cbase, c1 = c0 + 1;
                if (c0 > row_g0)     v0 = -1e30f;
                if (c1 > row_g0)     v1 = -1e30f;
                if (c0 > row_g0 + 8) v2 = -1e30f;
                if (c1 > row_g0 + 8) v3 = -1e30f;
                s[j][0] = v0; s[j][1] = v1; s[j][2] = v2; s[j][3] = v3;
                mx0 = fmaxf(mx0, fmaxf(v0, v1));
                mx1 = fmaxf(mx1, fmaxf(v2, v3));
            }
        } else {
#pragma unroll
            for (int j = 0; j < 8; ++j) {
                int cbase = j * 8 + qd * 2;
                uchar2 pb = *(const uchar2*)&kb[cbase];
                float pen0 = pb.x ? -1e30f : 0.0f;
                float pen1 = pb.y ? -1e30f : 0.0f;
                float v0 = s[j][0] * scl2 + pen0;
                float v1 = s[j][1] * scl2 + pen1;
                float v2 = s[j][2] * scl2 + pen0;
                float v3 = s[j][3] * scl2 + pen1;
                s[j][0] = v0; s[j][1] = v1; s[j][2] = v2; s[j][3] = v3;
                mx0 = fmaxf(mx0, fmaxf(v0, v1));
                mx1 = fmaxf(mx1, fmaxf(v2, v3));
            }
        }
        mx0 = fmaxf(mx0, __shfl_xor_sync(0xffffffffu, mx0, 1));
        mx0 = fmaxf(mx0, __shfl_xor_sync(0xffffffffu, mx0, 2));
        mx1 = fmaxf(mx1, __shfl_xor_sync(0xffffffffu, mx1, 1));
        mx1 = fmaxf(mx1, __shfl_xor_sync(0xffffffffu, mx1, 2));

        float mn0 = fmaxf(m0, mx0), mn1 = fmaxf(m1, mx1);
        float corr0 = exp2f(m0 - mn0), corr1 = exp2f(m1 - mn1);
        float sum0 = 0.0f, sum1 = 0.0f;
#pragma unroll
        for (int j = 0; j < 8; ++j) {
            s[j][0] = exp2f(s[j][0] - mn0);
            s[j][1] = exp2f(s[j][1] - mn0);
            s[j][2] = exp2f(s[j][2] - mn1);
            s[j][3] = exp2f(s[j][3] - mn1);
            sum0 += s[j][0] + s[j][1];
            sum1 += s[j][2] + s[j][3];
        }
        sum0 += __shfl_xor_sync(0xffffffffu, sum0, 1);
        sum0 += __shfl_xor_sync(0xffffffffu, sum0, 2);
        sum1 += __shfl_xor_sync(0xffffffffu, sum1, 1);
        sum1 += __shfl_xor_sync(0xffffffffu, sum1, 2);
        l0 = l0 * corr0 + sum0;  m0 = mn0;
        l1 = l1 * corr1 + sum1;  m1 = mn1;

#pragma unroll
        for (int j = 0; j < 8; ++j) {
            o[j][0] *= corr0; o[j][1] *= corr0;
            o[j][2] *= corr1; o[j][3] *= corr1;
        }

        // P (fp16) A-fragments — register repack (s dead afterwards)
        unsigned aP[4][4];
#pragma unroll
        for (int kk = 0; kk < 4; ++kk) {
            __half2 h0 = __floats2half2_rn(s[2*kk][0],   s[2*kk][1]);
            __half2 h1 = __floats2half2_rn(s[2*kk][2],   s[2*kk][3]);
            __half2 h2 = __floats2half2_rn(s[2*kk+1][0], s[2*kk+1][1]);
            __half2 h3 = __floats2half2_rn(s[2*kk+1][2], s[2*kk+1][3]);
            aP[kk][0] = *(unsigned*)&h0;
            aP[kk][1] = *(unsigned*)&h1;
            aP[kk][2] = *(unsigned*)&h2;
            aP[kk][3] = *(unsigned*)&h3;
        }

        // ---- pipeline turn: make tile kt+1 ready, prefetch kt+2, QK(kt+1) ----
        if (kt < qt) {
            cp_wait<0>();          // load(kt+1) done (issued a full iter ago)
            __syncthreads();       // visibility + all warps past tile kt-1 use
            if (kt + 2 <= qt) load_kv((kt + 2) % 3, kt + 2);
            qk_tile((kt + 1) % 3); // overlaps with PV below
        }

        // ---- O += P @ V (tile kt) ----
        const unsigned vb = vsaddr + (unsigned)((kt % 3) * KVBUF) + vrow_b;
#pragma unroll
        for (int kk = 0; kk < 4; ++kk) {
            const unsigned rowb = vb + (unsigned)(kk * 2048);
#pragma unroll
            for (int jp = 0; jp < 4; ++jp) {
                unsigned d0, d1, d2, d3;
                ldsm_x4_trans(d0, d1, d2, d3, rowb + voff[jp]);
                mma16816(o[2*jp],     aP[kk], d0, d1);
                mma16816(o[2*jp + 1], aP[kk], d2, d3);
            }
        }
    }

    // ---- normalize + write out ----
    float inv0 = 1.0f / l0, inv1 = 1.0f / l1;
    const size_t orow0 = ((size_t)b * SQn + row_g0) * Dn + h * 64;
    const size_t orow1 = orow0 + 8 * (size_t)Dn;
#pragma unroll
    for (int j = 0; j < 8; ++j) {
        __half2 w0 = __floats2half2_rn(o[j][0] * inv0, o[j][1] * inv0);
        __half2 w1 = __floats2half2_rn(o[j][2] * inv1, o[j][3] * inv1);
        *(__half2*)&Out[orow0 + j*8 + qd*2] = w0;
        *(__half2*)&Out[orow1 + j*8 + qd*2] = w1;
    }
}

// ---------------------------------------------------------------------------
// Launch
// ---------------------------------------------------------------------------
extern "C" void kernel_launch(void* const* d_in, const int* in_sizes, int n_in,
                              void* d_out, int out_size)
{
    const float* query = (const float*)d_in[0];
    const float* key   = (const float*)d_in[1];
    const float* value = (const float*)d_in[2];
    // d_in[3] = attn_mask (causal) — applied analytically in attn_kernel
    const unsigned char* kpm = (const unsigned char*)d_in[4];
    const float* Wq = (const float*)d_in[5];
    const float* bq = (const float*)d_in[6];
    const float* Wk = (const float*)d_in[7];
    const float* bk = (const float*)d_in[8];
    const float* Wv = (const float*)d_in[9];
    const float* bv = (const float*)d_in[10];
    const float* Wo = (const float*)d_in[11];
    const float* bo = (const float*)d_in[12];

    void *p_hq, *p_hk, *p_hv, *p_wq, *p_wk, *p_wv, *p_wo;
    void *p_q16, *p_k16, *p_v16, *p_attn;
    cudaGetSymbolAddress(&p_hq, g_hq);
    cudaGetSymbolAddress(&p_hk, g_hk);
    cudaGetSymbolAddress(&p_hv, g_hv);
    cudaGetSymbolAddress(&p_wq, g_wq);
    cudaGetSymbolAddress(&p_wk, g_wk);
    cudaGetSymbolAddress(&p_wv, g_wv);
    cudaGetSymbolAddress(&p_wo, g_wo);
    cudaGetSymbolAddress(&p_q16, g_q16);
    cudaGetSymbolAddress(&p_k16, g_k16);
    cudaGetSymbolAddress(&p_v16, g_v16);
    cudaGetSymbolAddress(&p_attn, g_attn);

    const int n4in = Bn * SQn * Dn / 4;
    const int n4w  = Dn * Dn / 4;
    const int tpb = 256, vpb = tpb * 4;

    dim3 fin_grid((n4in + vpb - 1) / vpb, 1, 3);
    f2h3_kernel<<<fin_grid, tpb>>>(
        (const float4*)query, (const float4*)key, (const float4*)value,
        (__half2*)p_hq, (__half2*)p_hk, (__half2*)p_hv, n4in);

    dim3 fw_grid((n4w + vpb - 1) / vpb, 1, 4);
    f2h4_kernel<<<fw_grid, tpb>>>(
        (const float4*)Wq, (const float4*)Wk, (const float4*)Wv, (const float4*)Wo,
        (__half2*)p_wq, (__half2*)p_wk, (__half2*)p_wv, (__half2*)p_wo, n4w);

    cudaFuncSetAttribute(gemm_qkv, cudaFuncAttributeMaxDynamicSharedMemorySize, GSMEM);
    cudaFuncSetAttribute(gemm_out, cudaFuncAttributeMaxDynamicSharedMemorySize, GSMEM);
    cudaFuncSetAttribute(attn_kernel, cudaFuncAttributeMaxDynamicSharedMemorySize, ATT_SMEM);

    dim3 qkv_grid(Dn / GBN, Mrows / GBM, 3);   // (4, 64, 3) = 768 CTAs
    gemm_qkv<<<qkv_grid, 256, GSMEM>>>(
        (const __half*)p_hq, (const __half*)p_hk, (const __half*)p_hv,
        (const __half*)p_wq, (const __half*)p_wk, (const __half*)p_wv,
        bq, bk, bv,
        (__half*)p_q16, (__half*)p_k16, (__half*)p_v16);

    attn_kernel<<<dim3(SQn / 64, Hn, Bn), 128, ATT_SMEM>>>(
        (const __half*)p_q16, (const __half*)p_k16, (const __half*)p_v16,
        kpm, (__half*)p_attn);

    dim3 ogrid(Dn / GBN, Mrows / GBM, 1);      // (4, 64)
    gemm_out<<<ogrid, 256, GSMEM>>>(
        (const __half*)p_attn, (const __half*)p_wo, bo, (float*)d_out);
}